// round 16
// baseline (speedup 1.0000x reference)
#include <cuda_runtime.h>
#include <cuda_fp16.h>

#define HH 128
#define WW 128
#define PLANE (HH*WW)
#define CYC 21
#define TW 16
#define TH 8
#define HLW 26
#define HLH 13
#define NCELL 338           // 13*26
#define NCP 352             // padded cells (44 x 8)
#define NT 256
#define NBLK 512

#define YROW 80             // 32 f16 = 64B + 16B pad
#define OFF_YH 0            // B matrix: 352 x YROW
#define OFF_A  28160        // A matrix: 128 x YROW
#define OFF_D  38400        // D: 128 rows x DROW bytes (f16 cells 0..351)
#define DROW   720
#define OFF_X  130560       // 338 cells x 16B: (h2 x0dup, x1dup, x2dup, 0)
#define OFF_TAB 135968      // 4 groups x 18 x uint2
#define SMEM_TOTAL 136576

typedef unsigned int u32;

__device__ float g_part[NBLK];
__device__ unsigned int g_cnt = 0;

__device__ __forceinline__ float ex2f(float v) {
    float r; asm("ex2.approx.ftz.f32 %0,%1;" : "=f"(r) : "f"(v)); return r;
}
__device__ __forceinline__ u32 hex2(u32 a) {
    u32 d; asm("ex2.approx.f16x2 %0,%1;" : "=r"(d) : "r"(a)); return d;
}
__device__ __forceinline__ u32 hadd2u(u32 a, u32 b) {
    u32 d; asm("add.rn.f16x2 %0,%1,%2;" : "=r"(d) : "r"(a), "r"(b)); return d;
}
__device__ __forceinline__ u32 hmul2u(u32 a, u32 b) {
    u32 d; asm("mul.rn.f16x2 %0,%1,%2;" : "=r"(d) : "r"(a), "r"(b)); return d;
}
__device__ __forceinline__ u32 hfma2u(u32 a, u32 b, u32 c) {
    u32 d; asm("fma.rn.f16x2 %0,%1,%2,%3;" : "=r"(d) : "r"(a), "r"(b), "r"(c)); return d;
}
__device__ __forceinline__ u32 prmt2(u32 a, u32 b, u32 sel) {
    u32 d; asm("prmt.b32 %0,%1,%2,%3;" : "=r"(d) : "r"(a), "r"(b), "r"(sel)); return d;
}
__device__ __forceinline__ u32 smem_u32(const void* p) {
    u32 a; asm("{ .reg .u64 t; cvta.to.shared.u64 t, %1; cvt.u32.u64 %0, t; }" : "=r"(a) : "l"(p));
    return a;
}
__device__ __forceinline__ u32 pack_h2(float lo, float hi) {
    u32 d; asm("cvt.rn.f16x2.f32 %0,%1,%2;" : "=r"(d) : "f"(hi), "f"(lo)); return d;
}
__device__ __forceinline__ uint4 lds128(u32 a) {
    uint4 v; asm volatile("ld.shared.v4.b32 {%0,%1,%2,%3},[%4];"
        : "=r"(v.x), "=r"(v.y), "=r"(v.z), "=r"(v.w) : "r"(a)); return v;
}
__device__ __forceinline__ uint2 lds64(u32 a) {
    uint2 v; asm volatile("ld.shared.v2.b32 {%0,%1},[%2];" : "=r"(v.x), "=r"(v.y) : "r"(a)); return v;
}
__device__ __forceinline__ u32 lds_u16(u32 a) {
    u32 d; asm volatile("ld.shared.u16 %0,[%1];" : "=r"(d) : "r"(a)); return d;
}
__device__ __forceinline__ void sts_u32(u32 a, u32 v) {
    asm volatile("st.shared.b32 [%0],%1;" :: "r"(a), "r"(v) : "memory");
}
__device__ __forceinline__ void sts128(u32 a, u32 x, u32 y, u32 z, u32 w) {
    asm volatile("st.shared.v4.b32 [%0],{%1,%2,%3,%4};" :: "r"(a), "r"(x), "r"(y), "r"(z), "r"(w) : "memory");
}
__device__ __forceinline__ void ldm4(u32& r0, u32& r1, u32& r2, u32& r3, u32 a) {
    asm volatile("ldmatrix.sync.aligned.m8n8.x4.shared.b16 {%0,%1,%2,%3},[%4];"
        : "=r"(r0), "=r"(r1), "=r"(r2), "=r"(r3) : "r"(a));
}
__device__ __forceinline__ void mma16816(float& d0, float& d1, float& d2, float& d3,
                                         u32 a0, u32 a1, u32 a2, u32 a3, u32 b0, u32 b1) {
    asm volatile("mma.sync.aligned.m16n8k16.row.col.f32.f16.f16.f32 "
                 "{%0,%1,%2,%3},{%4,%5,%6,%7},{%8,%9},{%0,%1,%2,%3};"
                 : "+f"(d0), "+f"(d1), "+f"(d2), "+f"(d3)
                 : "r"(a0), "r"(a1), "r"(a2), "r"(a3), "r"(b0), "r"(b1));
}

#define XSCALE 8.493218003f               // sqrt(50*log2(e))
#define CXY   (-0.020037431123458f)       // -log2(e)/72
#define SGN2  0x80008000u

__device__ __forceinline__ float hw_exy(int di, int dj) {
    if (dj >= -5 && dj <= 5 && (di >= 1 || dj >= 1))
        return 2.0f * __expf(-(float)(di * di + dj * dj) * (1.0f / 72.0f));
    return 0.0f;
}

__global__ __launch_bounds__(NT, 1) void crf_mma(const float* __restrict__ x,
                                                 const float* __restrict__ y,
                                                 float* __restrict__ out) {
    extern __shared__ char smem[];
    const u32 sb = smem_u32(smem);
    const int tid = threadIdx.x;
    const int warp = tid >> 5, lane = tid & 31;
    const int th0 = blockIdx.y * TH, tw0 = blockIdx.x * TW;
    const int bz = blockIdx.z;
    const float* xb = x + (size_t)bz * 3 * PLANE;
    const float* yb = y + (size_t)bz * CYC * PLANE;

    __shared__ float red[8];
    __shared__ int lastflag;

    // ---- phase 0: zero B matrix region ----
    for (int i = tid; i < (NCP * YROW) / 16; i += NT)
        sts128(sb + OFF_YH + i * 16, 0u, 0u, 0u, 0u);
    __syncthreads();

    // ---- phase 1: fill B (y halo, f16, flag ch21=+1), Xh, TAB ----
    for (int cell = tid; cell < NCELL; cell += NT) {
        int r = cell / HLW, c = cell - r * HLW;
        int gh = th0 + r, gw = tw0 - 5 + c;
        // Xh: scaled x, duplicated halves
        float x0 = 0.f, x1 = 0.f, x2 = 0.f;
        bool v = (gh < HH) && ((unsigned)gw < WW);
        int gi = gh * WW + gw;
        if (v) {
            x0 = xb[gi] * XSCALE; x1 = xb[PLANE + gi] * XSCALE; x2 = xb[2 * PLANE + gi] * XSCALE;
        }
        sts128(sb + OFF_X + cell * 16, pack_h2(x0, x0), pack_h2(x1, x1), pack_h2(x2, x2), 0u);
        if (v) {
            u32 base = sb + OFF_YH + cell * YROW;
            #pragma unroll
            for (int k = 0; k < 10; ++k)
                sts_u32(base + 4 * k, pack_h2(yb[(2 * k) * PLANE + gi], yb[(2 * k + 1) * PLANE + gi]));
            sts_u32(base + 40, pack_h2(yb[20 * PLANE + gi], 1.0f));   // ch20, flag=+1
        }
    }
    for (int t = tid; t < 72; t += NT) {
        int g2 = t / 18, rem = t - g2 * 18;
        int r = rem / 6, m = rem - r * 6;
        int di = (g2 >> 1) * 3 + r;
        int jj = (g2 & 1) + 2 * m;
        float t0 = hw_exy(di, jj - 5);     // pc0
        float t1 = hw_exy(di, jj - 6);     // pc1
        u32 h9 = pack_h2(0.9f * t0, 0.9f * t1);
        u32 h1 = pack_h2(0.1f * t0, 0.1f * t1);
        asm volatile("st.shared.v2.b32 [%0],{%1,%2};" :: "r"(sb + OFF_TAB + t * 8), "r"(h9), "r"(h1) : "memory");
    }
    __syncthreads();

    // ---- phase 2: A = tile pixels copied from B rows, flag flipped to -1 ----
    if (tid < 128) {
        int p = tid;
        int cellp = (p >> 4) * HLW + (p & 15) + 5;
        u32 src = sb + OFF_YH + cellp * YROW;
        u32 dst = sb + OFF_A + p * YROW;
        uint4 q0 = lds128(src), q1 = lds128(src + 16), q2 = lds128(src + 32);
        q2.z ^= 0x80000000u;               // pair 10 hi-half (ch21): +1 -> -1
        sts128(dst, q0.x, q0.y, q0.z, q0.w);
        sts128(dst + 16, q1.x, q1.y, q1.z, q1.w);
        sts128(dst + 32, q2.x, q2.y, q2.z, q2.w);
        sts128(dst + 48, 0u, 0u, 0u, 0u);
    }
    __syncthreads();

    // ---- phase 3: MMA -> D[pixel][cell] f16 ----
    {
        const int arow = (lane & 7) + ((lane >> 3) & 1) * 8;
        const u32 akoff = (u32)((lane >> 4) * 16);
        const u32 aaddr = sb + OFF_A + (u32)((warp * 16 + arow) * YROW) + akoff;
        u32 a0, a1, a2, a3, a4, a5, a6, a7;
        ldm4(a0, a1, a2, a3, aaddr);
        ldm4(a4, a5, a6, a7, aaddr + 32);

        const int brow = (lane & 7) + ((lane >> 4) & 1) * 8;
        const u32 bkoff = (u32)(((lane >> 3) & 1) * 16);
        const int prow = warp * 16 + (lane >> 2);
        const u32 dbase0 = sb + OFF_D + (u32)(prow * DROW) + (u32)(2 * (lane & 3)) * 2u;
        const u32 dbase1 = dbase0 + 8u * DROW;

        #pragma unroll 2
        for (int nt = 0; nt < 22; ++nt) {
            const u32 baddr = sb + OFF_YH + (u32)((nt * 16 + brow) * YROW) + bkoff;
            u32 b0, b1, b2, b3, b4, b5, b6, b7;
            ldm4(b0, b1, b2, b3, baddr);
            ldm4(b4, b5, b6, b7, baddr + 32);
            float d0 = 0.f, d1 = 0.f, d2 = 0.f, d3 = 0.f;
            float e0 = 0.f, e1 = 0.f, e2 = 0.f, e3 = 0.f;
            mma16816(d0, d1, d2, d3, a0, a1, a2, a3, b0, b1);
            mma16816(d0, d1, d2, d3, a4, a5, a6, a7, b4, b5);
            mma16816(e0, e1, e2, e3, a0, a1, a2, a3, b2, b3);
            mma16816(e0, e1, e2, e3, a4, a5, a6, a7, b6, b7);
            const u32 co = (u32)(nt * 32);
            sts_u32(dbase0 + co, pack_h2(d0, d1));
            sts_u32(dbase1 + co, pack_h2(d2, d3));
            sts_u32(dbase0 + co + 16, pack_h2(e0, e1));
            sts_u32(dbase1 + co + 16, pack_h2(e2, e3));
        }
    }
    __syncthreads();

    // ---- phase 4: K-path mainloop ----
    const int g = tid >> 6, gj = g & 1, gi2 = g >> 1;
    const int pid = tid & 63, px = pid & 7, py = pid >> 3;
    const int p0 = py * 16 + 2 * px;
    const u32 dD = sb + OFF_D + (u32)(p0 * DROW);
    const int cc0 = py * HLW + 2 * px + 5;
    const uint4 xq0 = lds128(sb + OFF_X + cc0 * 16);
    const uint4 xq1 = lds128(sb + OFF_X + (cc0 + 1) * 16);
    const u32 ng0 = prmt2(xq0.x, xq1.x, 0x5410u) ^ SGN2;   // (-x0 pc0, -x0 pc1)
    const u32 ng1 = prmt2(xq0.y, xq1.y, 0x5410u) ^ SGN2;
    const u32 ng2 = prmt2(xq0.z, xq1.z, 0x5410u) ^ SGN2;

    u32 acc = 0u;
    #pragma unroll
    for (int r = 0; r < 3; ++r) {
        const int rb = (py + gi2 * 3 + r) * HLW + 2 * px + gj;
        #pragma unroll
        for (int m = 0; m < 6; ++m) {
            const int cell = rb + 2 * m;
            const uint4 xq = lds128(sb + OFF_X + cell * 16);
            const uint2 tt = lds64(sb + OFF_TAB + (u32)((g * 18 + r * 6 + m) * 8));
            const u32 d0 = hadd2u(xq.x, ng0);
            const u32 d1 = hadd2u(xq.y, ng1);
            const u32 d2 = hadd2u(xq.z, ng2);
            u32 s = hmul2u(d0, d0); s = hfma2u(d1, d1, s); s = hfma2u(d2, d2, s);
            const u32 E = hex2(s ^ SGN2);
            const u32 Kh = hfma2u(E, tt.x, tt.y);          // (K_pc0, K_pc1)
            const u32 q0 = lds_u16(dD + (u32)(cell * 2));
            const u32 q1 = lds_u16(dD + (u32)(DROW + cell * 2));
            const u32 Dp = prmt2(q0, q1, 0x5410u);         // (D_p0, D_p1)
            acc = hfma2u(Kh, Dp, acc);
        }
    }

    float acc2;
    {
        __half2 a = *(__half2*)&acc;
        acc2 = __low2float(a) + __high2float(a);
    }
    float part = -acc2;
    if (g == 0) {
        u32 sxs = hmul2u(ng0, ng0);
        sxs = hfma2u(ng1, ng1, sxs);
        sxs = hfma2u(ng2, ng2, sxs);
        const u32 Ex = hex2(sxs ^ SGN2);
        const __half2 Exh = *(__half2*)&Ex;
        const int h = th0 + py;
        const int rv = min(5, 127 - h) + min(5, h) + 1;
        #pragma unroll
        for (int pc = 0; pc < 2; ++pc) {
            const int w = tw0 + 2 * px + pc;
            const int cv = min(5, 127 - w) + min(5, w) + 1;
            const int noob = 121 - rv * cv;
            if (noob > 0) {
                const float Ec = pc ? __high2float(Exh) : __low2float(Exh);
                const float F = fmaf(0.9f, Ec, 0.1f);
                part += (float)noob * ex2f((float)(h * h + w * w) * CXY) * F;
            }
        }
    }

    // ---- reduction (deterministic, fused final) ----
    #pragma unroll
    for (int o = 16; o > 0; o >>= 1) part += __shfl_xor_sync(0xffffffffu, part, o);
    if (lane == 0) red[warp] = part;
    __syncthreads();
    const int bid = ((bz * gridDim.y) + blockIdx.y) * gridDim.x + blockIdx.x;
    if (tid == 0) {
        float s = 0.f;
        #pragma unroll
        for (int wi = 0; wi < 8; ++wi) s += red[wi];
        g_part[bid] = s;
        __threadfence();
        unsigned old = atomicAdd(&g_cnt, 1u);
        lastflag = (old == NBLK - 1) ? 1 : 0;
    }
    __syncthreads();
    if (lastflag) {
        float v = g_part[tid] + g_part[tid + 256];
        #pragma unroll
        for (int o = 16; o > 0; o >>= 1) v += __shfl_xor_sync(0xffffffffu, v, o);
        if (lane == 0) red[warp] = v;
        __syncthreads();
        if (tid == 0) {
            float s = 0.f;
            #pragma unroll
            for (int wi = 0; wi < 8; ++wi) s += red[wi];
            out[0] = s * (1.0f / 65536.0f);
            g_cnt = 0;
        }
    }
}

extern "C" void kernel_launch(void* const* d_in, const int* in_sizes, int n_in,
                              void* d_out, int out_size) {
    const float* x = (const float*)d_in[0];
    const float* y = (const float*)d_in[1];
    (void)in_sizes; (void)n_in; (void)out_size;
    cudaFuncSetAttribute(crf_mma, cudaFuncAttributeMaxDynamicSharedMemorySize, SMEM_TOTAL);
    dim3 grid(WW / TW, HH / TH, 4);
    crf_mma<<<grid, NT, SMEM_TOTAL>>>(x, y, (float*)d_out);
}

// round 17
// speedup vs baseline: 1.3222x; 1.3222x over previous
#include <cuda_runtime.h>
#include <cuda_fp16.h>

#define HH 128
#define WW 128
#define PLANE (HH*WW)
#define CYC 21
#define TW 16
#define TH 8
#define HLW 26
#define HLH 13
#define NCELL 338           // 13*26
#define NCP 352             // padded B rows
#define NT 256
#define NBLK 512

#define YROW 80             // 32 f16 = 64B + 16B pad
#define OFF_YH 0            // B matrix: 352 x YROW = 28160
#define OFF_A  28160        // A matrix: 128 x YROW = 10240
#define OFF_D  38400        // D: 8 warps x 16 px x DPITCH
#define DPITCH 336          // 160 cells x 2B + 16B pad
#define OFF_X  81408        // 338 cells x 16B
#define OFF_TAB 86816       // 72 x uint2
#define SMEM_TOTAL 87424

typedef unsigned int u32;

__device__ float g_part[NBLK];
__device__ unsigned int g_cnt = 0;

__device__ __forceinline__ float ex2f(float v) {
    float r; asm("ex2.approx.ftz.f32 %0,%1;" : "=f"(r) : "f"(v)); return r;
}
__device__ __forceinline__ u32 hex2(u32 a) {
    u32 d; asm("ex2.approx.f16x2 %0,%1;" : "=r"(d) : "r"(a)); return d;
}
__device__ __forceinline__ u32 hadd2u(u32 a, u32 b) {
    u32 d; asm("add.rn.f16x2 %0,%1,%2;" : "=r"(d) : "r"(a), "r"(b)); return d;
}
__device__ __forceinline__ u32 hmul2u(u32 a, u32 b) {
    u32 d; asm("mul.rn.f16x2 %0,%1,%2;" : "=r"(d) : "r"(a), "r"(b)); return d;
}
__device__ __forceinline__ u32 hfma2u(u32 a, u32 b, u32 c) {
    u32 d; asm("fma.rn.f16x2 %0,%1,%2,%3;" : "=r"(d) : "r"(a), "r"(b), "r"(c)); return d;
}
__device__ __forceinline__ u32 prmt2(u32 a, u32 b, u32 sel) {
    u32 d; asm("prmt.b32 %0,%1,%2,%3;" : "=r"(d) : "r"(a), "r"(b), "r"(sel)); return d;
}
__device__ __forceinline__ u32 smem_u32(const void* p) {
    u32 a; asm("{ .reg .u64 t; cvta.to.shared.u64 t, %1; cvt.u32.u64 %0, t; }" : "=r"(a) : "l"(p));
    return a;
}
__device__ __forceinline__ u32 pack_h2(float lo, float hi) {
    u32 d; asm("cvt.rn.f16x2.f32 %0,%1,%2;" : "=r"(d) : "f"(hi), "f"(lo)); return d;
}
__device__ __forceinline__ uint4 lds128(u32 a) {
    uint4 v; asm volatile("ld.shared.v4.b32 {%0,%1,%2,%3},[%4];"
        : "=r"(v.x), "=r"(v.y), "=r"(v.z), "=r"(v.w) : "r"(a)); return v;
}
__device__ __forceinline__ uint2 lds64(u32 a) {
    uint2 v; asm volatile("ld.shared.v2.b32 {%0,%1},[%2];" : "=r"(v.x), "=r"(v.y) : "r"(a)); return v;
}
__device__ __forceinline__ u32 lds_u16(u32 a) {
    u32 d; asm volatile("ld.shared.u16 %0,[%1];" : "=r"(d) : "r"(a)); return d;
}
__device__ __forceinline__ void sts_u32(u32 a, u32 v) {
    asm volatile("st.shared.b32 [%0],%1;" :: "r"(a), "r"(v) : "memory");
}
__device__ __forceinline__ void sts128(u32 a, u32 x, u32 y, u32 z, u32 w) {
    asm volatile("st.shared.v4.b32 [%0],{%1,%2,%3,%4};" :: "r"(a), "r"(x), "r"(y), "r"(z), "r"(w) : "memory");
}
__device__ __forceinline__ void ldm4(u32& r0, u32& r1, u32& r2, u32& r3, u32 a) {
    asm volatile("ldmatrix.sync.aligned.m8n8.x4.shared.b16 {%0,%1,%2,%3},[%4];"
        : "=r"(r0), "=r"(r1), "=r"(r2), "=r"(r3) : "r"(a));
}
__device__ __forceinline__ void mma16816(float& d0, float& d1, float& d2, float& d3,
                                         u32 a0, u32 a1, u32 a2, u32 a3, u32 b0, u32 b1) {
    asm volatile("mma.sync.aligned.m16n8k16.row.col.f32.f16.f16.f32 "
                 "{%0,%1,%2,%3},{%4,%5,%6,%7},{%8,%9},{%0,%1,%2,%3};"
                 : "+f"(d0), "+f"(d1), "+f"(d2), "+f"(d3)
                 : "r"(a0), "r"(a1), "r"(a2), "r"(a3), "r"(b0), "r"(b1));
}

#define XSCALE 8.493218003f               // sqrt(50*log2(e))
#define CXY   (-0.020037431123458f)       // -log2(e)/72
#define SGN2  0x80008000u

__device__ __forceinline__ float hw_exy(int di, int dj) {
    if (dj >= -5 && dj <= 5 && (di >= 1 || dj >= 1))
        return 2.0f * __expf(-(float)(di * di + dj * dj) * (1.0f / 72.0f));
    return 0.0f;
}

__global__ __launch_bounds__(NT, 2) void crf_mma(const float* __restrict__ x,
                                                 const float* __restrict__ y,
                                                 float* __restrict__ out) {
    extern __shared__ char smem[];
    const u32 sb = smem_u32(smem);
    const int tid = threadIdx.x;
    const int warp = tid >> 5, lane = tid & 31;
    const int th0 = blockIdx.y * TH, tw0 = blockIdx.x * TW;
    const int bz = blockIdx.z;
    const float* xb = x + (size_t)bz * 3 * PLANE;
    const float* yb = y + (size_t)bz * CYC * PLANE;

    __shared__ float red[8];
    __shared__ int lastflag;

    // ---- phase 0: zero B matrix region ----
    for (int i = tid; i < (NCP * YROW) / 16; i += NT)
        sts128(sb + OFF_YH + i * 16, 0u, 0u, 0u, 0u);
    __syncthreads();

    // ---- phase 1: fill B (y halo f16, flag ch21=+1), Xh, TAB ----
    for (int cell = tid; cell < NCELL; cell += NT) {
        int r = cell / HLW, c = cell - r * HLW;
        int gh = th0 + r, gw = tw0 - 5 + c;
        float x0 = 0.f, x1 = 0.f, x2 = 0.f;
        bool v = (gh < HH) && ((unsigned)gw < WW);
        int gi = gh * WW + gw;
        if (v) {
            x0 = xb[gi] * XSCALE; x1 = xb[PLANE + gi] * XSCALE; x2 = xb[2 * PLANE + gi] * XSCALE;
        }
        sts128(sb + OFF_X + cell * 16, pack_h2(x0, x0), pack_h2(x1, x1), pack_h2(x2, x2), 0u);
        if (v) {
            u32 base = sb + OFF_YH + cell * YROW;
            #pragma unroll
            for (int k = 0; k < 10; ++k)
                sts_u32(base + 4 * k, pack_h2(yb[(2 * k) * PLANE + gi], yb[(2 * k + 1) * PLANE + gi]));
            sts_u32(base + 40, pack_h2(yb[20 * PLANE + gi], 1.0f));   // ch20 + flag
        }
    }
    for (int t = tid; t < 72; t += NT) {
        int g2 = t / 18, rem = t - g2 * 18;
        int r = rem / 6, m = rem - r * 6;
        int di = (g2 >> 1) * 3 + r;
        int jj = (g2 & 1) + 2 * m;
        float t0 = hw_exy(di, jj - 5);     // pc0
        float t1 = hw_exy(di, jj - 6);     // pc1
        u32 h9 = pack_h2(0.9f * t0, 0.9f * t1);
        u32 h1 = pack_h2(0.1f * t0, 0.1f * t1);
        asm volatile("st.shared.v2.b32 [%0],{%1,%2};" :: "r"(sb + OFF_TAB + t * 8), "r"(h9), "r"(h1) : "memory");
    }
    __syncthreads();

    // ---- phase 2: A = tile pixel rows from B, flag -> -1 ----
    if (tid < 128) {
        int p = tid;
        int cellp = (p >> 4) * HLW + (p & 15) + 5;
        u32 src = sb + OFF_YH + cellp * YROW;
        u32 dst = sb + OFF_A + p * YROW;
        uint4 q0 = lds128(src), q1 = lds128(src + 16), q2 = lds128(src + 32);
        q2.z ^= 0x80000000u;               // ch21: +1 -> -1
        sts128(dst, q0.x, q0.y, q0.z, q0.w);
        sts128(dst + 16, q1.x, q1.y, q1.z, q1.w);
        sts128(dst + 32, q2.x, q2.y, q2.z, q2.w);
        sts128(dst + 48, 0u, 0u, 0u, 0u);
    }
    __syncthreads();

    // ---- phase 3: band-restricted MMA -> D[warp][16 px][160 cells] f16 ----
    {
        const int arow = (lane & 7) + ((lane >> 3) & 1) * 8;
        const u32 akoff = (u32)((lane >> 4) * 16);
        const u32 aaddr = sb + OFF_A + (u32)((warp * 16 + arow) * YROW) + akoff;
        u32 a0, a1, a2, a3, a4, a5, a6, a7;
        ldm4(a0, a1, a2, a3, aaddr);
        ldm4(a4, a5, a6, a7, aaddr + 32);

        const int brow = (lane & 7) + ((lane >> 4) & 1) * 8;
        const u32 bkoff = (u32)(((lane >> 3) & 1) * 16);
        const int bandbase = warp * HLW;            // first cell of this warp's band
        const u32 Dw = sb + OFF_D + (u32)(warp * 16 * DPITCH);
        const u32 dbase0 = Dw + (u32)((lane >> 2) * DPITCH) + (u32)((lane & 3) * 4);
        const u32 dbase1 = dbase0 + 8u * DPITCH;

        #pragma unroll 2
        for (int nt = 0; nt < 10; ++nt) {
            const u32 baddr = sb + OFF_YH + (u32)((bandbase + nt * 16 + brow) * YROW) + bkoff;
            u32 b0, b1, b2, b3, b4, b5, b6, b7;
            ldm4(b0, b1, b2, b3, baddr);
            ldm4(b4, b5, b6, b7, baddr + 32);
            float d0 = 0.f, d1 = 0.f, d2 = 0.f, d3 = 0.f;
            float e0 = 0.f, e1 = 0.f, e2 = 0.f, e3 = 0.f;
            mma16816(d0, d1, d2, d3, a0, a1, a2, a3, b0, b1);
            mma16816(d0, d1, d2, d3, a4, a5, a6, a7, b4, b5);
            mma16816(e0, e1, e2, e3, a0, a1, a2, a3, b2, b3);
            mma16816(e0, e1, e2, e3, a4, a5, a6, a7, b6, b7);
            const u32 co = (u32)(nt * 32);
            sts_u32(dbase0 + co, pack_h2(d0, d1));
            sts_u32(dbase1 + co, pack_h2(d2, d3));
            sts_u32(dbase0 + co + 16, pack_h2(e0, e1));
            sts_u32(dbase1 + co + 16, pack_h2(e2, e3));
        }
    }
    __syncthreads();

    // ---- phase 4: K-path mainloop ----
    const int g = tid >> 6, gj = g & 1, gi2 = g >> 1;
    const int pid = tid & 63, px = pid & 7, py = pid >> 3;
    const u32 dD = sb + OFF_D + (u32)((py * 16 + 2 * px) * DPITCH);
    const int cc0 = py * HLW + 2 * px + 5;
    const uint4 xq0 = lds128(sb + OFF_X + cc0 * 16);
    const uint4 xq1 = lds128(sb + OFF_X + (cc0 + 1) * 16);
    const u32 ng0 = prmt2(xq0.x, xq1.x, 0x5410u) ^ SGN2;
    const u32 ng1 = prmt2(xq0.y, xq1.y, 0x5410u) ^ SGN2;
    const u32 ng2 = prmt2(xq0.z, xq1.z, 0x5410u) ^ SGN2;

    u32 acc = 0u;
    #pragma unroll
    for (int r = 0; r < 3; ++r) {
        const int di = gi2 * 3 + r;
        const int rb = (py + di) * HLW + 2 * px + gj;       // absolute cell base
        const int rboff = di * HLW + 2 * px + gj;           // band-relative (cell - py*26)
        #pragma unroll
        for (int m = 0; m < 6; ++m) {
            const int cell = rb + 2 * m;
            const int celloff = rboff + 2 * m;
            const uint4 xq = lds128(sb + OFF_X + cell * 16);
            const uint2 tt = lds64(sb + OFF_TAB + (u32)((g * 18 + r * 6 + m) * 8));
            const u32 d0 = hadd2u(xq.x, ng0);
            const u32 d1 = hadd2u(xq.y, ng1);
            const u32 d2 = hadd2u(xq.z, ng2);
            u32 s = hmul2u(d0, d0); s = hfma2u(d1, d1, s); s = hfma2u(d2, d2, s);
            const u32 E = hex2(s ^ SGN2);
            const u32 Kh = hfma2u(E, tt.x, tt.y);          // (K_pc0, K_pc1)
            const u32 q0 = lds_u16(dD + (u32)(celloff * 2));
            const u32 q1 = lds_u16(dD + (u32)(DPITCH + celloff * 2));
            const u32 Dp = prmt2(q0, q1, 0x5410u);         // (D_p0, D_p1)
            acc = hfma2u(Kh, Dp, acc);
        }
    }

    float acc2;
    {
        __half2 a = *(__half2*)&acc;
        acc2 = __low2float(a) + __high2float(a);
    }
    float part = -acc2;
    if (g == 0) {
        u32 sxs = hmul2u(ng0, ng0);
        sxs = hfma2u(ng1, ng1, sxs);
        sxs = hfma2u(ng2, ng2, sxs);
        const u32 Ex = hex2(sxs ^ SGN2);
        const __half2 Exh = *(__half2*)&Ex;
        const int h = th0 + py;
        const int rv = min(5, 127 - h) + min(5, h) + 1;
        #pragma unroll
        for (int pc = 0; pc < 2; ++pc) {
            const int w = tw0 + 2 * px + pc;
            const int cv = min(5, 127 - w) + min(5, w) + 1;
            const int noob = 121 - rv * cv;
            if (noob > 0) {
                const float Ec = pc ? __high2float(Exh) : __low2float(Exh);
                const float F = fmaf(0.9f, Ec, 0.1f);
                part += (float)noob * ex2f((float)(h * h + w * w) * CXY) * F;
            }
        }
    }

    // ---- reduction (deterministic, fused final) ----
    #pragma unroll
    for (int o = 16; o > 0; o >>= 1) part += __shfl_xor_sync(0xffffffffu, part, o);
    if (lane == 0) red[warp] = part;
    __syncthreads();
    const int bid = ((bz * gridDim.y) + blockIdx.y) * gridDim.x + blockIdx.x;
    if (tid == 0) {
        float s = 0.f;
        #pragma unroll
        for (int wi = 0; wi < 8; ++wi) s += red[wi];
        g_part[bid] = s;
        __threadfence();
        unsigned old = atomicAdd(&g_cnt, 1u);
        lastflag = (old == NBLK - 1) ? 1 : 0;
    }
    __syncthreads();
    if (lastflag) {
        float v = g_part[tid] + g_part[tid + 256];
        #pragma unroll
        for (int o = 16; o > 0; o >>= 1) v += __shfl_xor_sync(0xffffffffu, v, o);
        if (lane == 0) red[warp] = v;
        __syncthreads();
        if (tid == 0) {
            float s = 0.f;
            #pragma unroll
            for (int wi = 0; wi < 8; ++wi) s += red[wi];
            out[0] = s * (1.0f / 65536.0f);
            g_cnt = 0;
        }
    }
}

extern "C" void kernel_launch(void* const* d_in, const int* in_sizes, int n_in,
                              void* d_out, int out_size) {
    const float* x = (const float*)d_in[0];
    const float* y = (const float*)d_in[1];
    (void)in_sizes; (void)n_in; (void)out_size;
    cudaFuncSetAttribute(crf_mma, cudaFuncAttributeMaxDynamicSharedMemorySize, SMEM_TOTAL);
    dim3 grid(WW / TW, HH / TH, 4);
    crf_mma<<<grid, NT, SMEM_TOTAL>>>(x, y, (float*)d_out);
}